// round 1
// baseline (speedup 1.0000x reference)
#include <cuda_runtime.h>

// NCA step: perception (id + sobel_x + sobel_y depthwise) -> MLP(48->128->16)
// -> stochastic update -> alive mask (pre & post 3x3 maxpool on channel 3).
//
// B=32, C=16, H=W=256, HID=128.

#define NB   32
#define NC   16
#define NH   256
#define NW   256
#define HID  128
#define TILE 16
#define TS   (TILE + 2)
#define HW   (NH * NW)

// scratch: channel-3 plane of x_new (8.4 MB, static device array — no allocs)
__device__ float g_ch3[NB * HW];

// dynamic smem layout (floats):
//   xs   : NC*TS*TS            = 5184
//   w1s  : HID*48              = 6144   (float4-aligned rows of 48)
//   w2ts : HID*16              = 2048   (transposed: [o][k])
//   b1s  : HID                 = 128
#define SM_XS    0
#define SM_W1    (SM_XS + NC * TS * TS)
#define SM_W2T   (SM_W1 + HID * 48)
#define SM_B1    (SM_W2T + HID * 16)
#define SM_FLOATS (SM_B1 + HID)
#define SM_BYTES (SM_FLOATS * 4)

extern __shared__ float smem[];

__global__ __launch_bounds__(256, 2)
void nca_main(const float* __restrict__ x, const float* __restrict__ ur,
              const float* __restrict__ w1, const float* __restrict__ b1,
              const float* __restrict__ w2, float* __restrict__ out) {
    float* xs   = smem + SM_XS;
    float* w1s  = smem + SM_W1;
    float* w2ts = smem + SM_W2T;
    float* b1s  = smem + SM_B1;

    const int b   = blockIdx.z;
    const int ty0 = blockIdx.y * TILE;
    const int tx0 = blockIdx.x * TILE;
    const int tid = threadIdx.y * TILE + threadIdx.x;  // 0..255

    // ---- stage weights ----
    {
        const float4* w1g  = (const float4*)w1;   // 1536 float4
        float4*       w1s4 = (float4*)w1s;
        #pragma unroll
        for (int i = tid; i < HID * 48 / 4; i += 256) w1s4[i] = w1g[i];
        // transpose w2 [16][128] -> w2t [128][16]
        #pragma unroll
        for (int i = tid; i < HID * 16; i += 256) {
            int o = i >> 4, k = i & 15;
            w2ts[i] = w2[k * HID + o];
        }
        if (tid < HID) b1s[tid] = b1[tid];
    }

    // ---- stage input tile (+1 halo, zero-padded) ----
    {
        const float* xb = x + (size_t)b * NC * HW;
        for (int i = tid; i < NC * TS * TS; i += 256) {
            int c  = i / (TS * TS);
            int r  = i - c * (TS * TS);
            int yy = r / TS, xx = r - (r / TS) * TS;
            int gy = ty0 + yy - 1, gx = tx0 + xx - 1;
            float v = 0.f;
            if (gy >= 0 && gy < NH && gx >= 0 && gx < NW)
                v = xb[c * HW + gy * NW + gx];
            xs[i] = v;
        }
    }
    __syncthreads();

    // ---- perception: y[3c]=id, y[3c+1]=sobel_x, y[3c+2]=sobel_y ----
    float y[48];
    {
        const int ly = threadIdx.y;  // tile-local row (halo offset applied below)
        const int lx = threadIdx.x;
        #pragma unroll
        for (int c = 0; c < NC; ++c) {
            const float* p = xs + c * TS * TS + ly * TS + lx;  // top-left of 3x3
            float a00 = p[0],        a01 = p[1],        a02 = p[2];
            float a10 = p[TS],       a11 = p[TS + 1],   a12 = p[TS + 2];
            float a20 = p[2 * TS],   a21 = p[2 * TS + 1], a22 = p[2 * TS + 2];
            y[3 * c + 0] = a11;
            y[3 * c + 1] = (a02 - a00 + 2.f * (a12 - a10) + a22 - a20) * 0.125f;
            y[3 * c + 2] = (a20 - a00 + 2.f * (a21 - a01) + a22 - a02) * 0.125f;
        }
    }

    // ---- MLP: h = relu(w1 @ y + b1); dx = w2 @ h ----
    float dx[NC];
    #pragma unroll
    for (int k = 0; k < NC; ++k) dx[k] = 0.f;

    #pragma unroll 2
    for (int o = 0; o < HID; ++o) {
        float hv = b1s[o];
        const float4* wr = (const float4*)(w1s + o * 48);
        #pragma unroll
        for (int q = 0; q < 12; ++q) {
            float4 wv = wr[q];
            hv = fmaf(wv.x, y[4 * q + 0], hv);
            hv = fmaf(wv.y, y[4 * q + 1], hv);
            hv = fmaf(wv.z, y[4 * q + 2], hv);
            hv = fmaf(wv.w, y[4 * q + 3], hv);
        }
        hv = fmaxf(hv, 0.f);
        const float4* w2r = (const float4*)(w2ts + o * 16);
        #pragma unroll
        for (int q = 0; q < 4; ++q) {
            float4 wv = w2r[q];
            dx[4 * q + 0] = fmaf(wv.x, hv, dx[4 * q + 0]);
            dx[4 * q + 1] = fmaf(wv.y, hv, dx[4 * q + 1]);
            dx[4 * q + 2] = fmaf(wv.z, hv, dx[4 * q + 2]);
            dx[4 * q + 3] = fmaf(wv.w, hv, dx[4 * q + 3]);
        }
    }

    // ---- stochastic update + store x_new ----
    const int gy = ty0 + threadIdx.y;
    const int gx = tx0 + threadIdx.x;
    const float u = (ur[(size_t)b * HW + gy * NW + gx] <= 0.5f) ? 1.f : 0.f;

    float* ob = out + (size_t)b * NC * HW + gy * NW + gx;
    #pragma unroll
    for (int c = 0; c < NC; ++c) {
        float v = fmaf(dx[c], u, y[3 * c]);   // x center + dx*update
        ob[c * HW] = v;
        if (c == 3) g_ch3[(size_t)b * HW + gy * NW + gx] = v;
    }
}

__global__ void nca_mask(const float* __restrict__ x, float* __restrict__ out) {
    int idx = blockIdx.x * blockDim.x + threadIdx.x;  // over B*H*W
    if (idx >= NB * HW) return;
    int b = idx / HW;
    int r = idx - b * HW;
    int i = r / NW, j = r - (r / NW) * NW;

    const float* x3 = x + ((size_t)b * NC + 3) * HW;
    const float* n3 = g_ch3 + (size_t)b * HW;
    float m0 = -1e30f, m1 = -1e30f;
    #pragma unroll
    for (int dy = -1; dy <= 1; ++dy) {
        int yy = i + dy;
        if (yy < 0 || yy >= NH) continue;
        #pragma unroll
        for (int dxx = -1; dxx <= 1; ++dxx) {
            int xx = j + dxx;
            if (xx < 0 || xx >= NW) continue;
            m0 = fmaxf(m0, x3[yy * NW + xx]);
            m1 = fmaxf(m1, n3[yy * NW + xx]);
        }
    }
    bool alive = (m0 > 0.1f) && (m1 > 0.1f);
    if (!alive) {
        float* ob = out + (size_t)b * NC * HW + r;
        #pragma unroll
        for (int c = 0; c < NC; ++c) ob[c * HW] = 0.f;
    }
}

extern "C" void kernel_launch(void* const* d_in, const int* in_sizes, int n_in,
                              void* d_out, int out_size) {
    const float* x  = (const float*)d_in[0];
    const float* ur = (const float*)d_in[1];
    const float* w1 = (const float*)d_in[2];
    const float* b1 = (const float*)d_in[3];
    const float* w2 = (const float*)d_in[4];
    float* out = (float*)d_out;

    cudaFuncSetAttribute(nca_main, cudaFuncAttributeMaxDynamicSharedMemorySize, SM_BYTES);

    dim3 grid(NW / TILE, NH / TILE, NB);
    dim3 block(TILE, TILE);
    nca_main<<<grid, block, SM_BYTES>>>(x, ur, w1, b1, w2, out);

    nca_mask<<<(NB * HW + 255) / 256, 256>>>(x, out);
}